// round 2
// baseline (speedup 1.0000x reference)
#include <cuda_runtime.h>
#include <cstdint>

// ---------------- problem constants ----------------
#define NN 50000
#define NE 800000
#define DD 300
#define NG 256
#define NL 5
#define F4C 75            // DD/4

// ---------------- GEMM tiling ----------------
#define BM 64
#define BK 25
#define NKT 12            // 300 / 25

// ---------------- scratch (static device allocs: allowed) ----------------
__device__ float g_x   [NN * DD];
__device__ float g_h   [NN * DD];
__device__ float g_hid [NN * DD];
__device__ float g_e   [(long long)NE * DD];   // 960 MB
__device__ float g_pool [NG * DD];
__device__ float g_pool2[NG * DD];
__device__ float g_cnt  [NG];

enum { A_GMEM = 0, A_NODE2 = 1, A_EDGE3 = 2 };
enum { E_BIAS = 0, E_RELU = 1, E_EMB = 2 };

// ============================================================
// Fused MLP GEMM:  Out[M,300] = Astage(M,300) @ W[300,300] (+bias)(+emb)(relu?)
//   A_GMEM : A read from gmem (already relu'd where needed)
//   A_NODE2: A[m,k] = relu(s0[m]*aW1[0,k] + s1[m]*aW1[1,k] + ab1[k])
//   A_EDGE3: A[m,k] = relu(sum_c s0[3m+c]*aW1[c,k] + ab1[k])
// BN covers all 300 output cols (padded to 320) so A streams from HBM once.
// ============================================================
template<int ASRC, int EPI>
__global__ __launch_bounds__(256)
void gemm300(const float* __restrict__ A,
             const float* __restrict__ s0, const float* __restrict__ s1,
             const float* __restrict__ aW1, const float* __restrict__ ab1,
             const float* __restrict__ W,  const float* __restrict__ bias,
             const float* __restrict__ emb, const int* __restrict__ zidx,
             float* __restrict__ Out, int M)
{
    __shared__ float As[BM][BK + 1];    // +1 pad -> conflict-free column reads
    __shared__ float Bs[BK][320];

    const int tid  = threadIdx.x;
    const int tx   = tid & 15;          // 16 col-threads
    const int ty   = tid >> 4;          // 16 row-threads
    const int row0 = blockIdx.x * BM;
    const int jb   = tx * 20;           // 20 contiguous cols per thread

    float acc[4][20];
#pragma unroll
    for (int r = 0; r < 4; r++)
#pragma unroll
        for (int c = 0; c < 20; c++) acc[r][c] = 0.f;

    for (int kt = 0; kt < NKT; kt++) {
        const int k0 = kt * BK;

        // ---- A tile: BM x BK (stage-1 MLP fused here) ----
#pragma unroll
        for (int l = 0; l < 7; l++) {
            int idx = tid + l * 256;
            if (idx < BM * BK) {
                int k  = idx % BK;
                int m  = idx / BK;
                int mg = row0 + m;
                int kg = k0 + k;
                float v = 0.f;
                if (mg < M) {
                    if (ASRC == A_GMEM) {
                        v = __ldg(&A[(long long)mg * DD + kg]);
                    } else if (ASRC == A_NODE2) {
                        float t = __ldg(&s0[mg]) * __ldg(&aW1[kg])
                                + __ldg(&s1[mg]) * __ldg(&aW1[DD + kg])
                                + __ldg(&ab1[kg]);
                        v = fmaxf(t, 0.f);
                    } else { // A_EDGE3
                        float e0 = __ldg(&s0[mg * 3 + 0]);
                        float e1 = __ldg(&s0[mg * 3 + 1]);
                        float e2 = __ldg(&s0[mg * 3 + 2]);
                        float t = e0 * __ldg(&aW1[kg])
                                + e1 * __ldg(&aW1[DD + kg])
                                + e2 * __ldg(&aW1[2 * DD + kg])
                                + __ldg(&ab1[kg]);
                        v = fmaxf(t, 0.f);
                    }
                }
                As[m][k] = v;
            }
        }

        // ---- B tile: BK x 320 (cols >=300 zero-filled) ----
#pragma unroll
        for (int l = 0; l < 8; l++) {
            int idx = tid + l * 256;
            if (idx < BK * 80) {
                int k  = idx / 80;
                int j4 = idx % 80;
                float4 v = make_float4(0.f, 0.f, 0.f, 0.f);
                if (j4 < 75) v = *(const float4*)&W[(k0 + k) * DD + 4 * j4];
                *(float4*)&Bs[k][4 * j4] = v;
            }
        }
        __syncthreads();

        // ---- compute: 80 FMA per thread per k ----
#pragma unroll 5
        for (int k = 0; k < BK; k++) {
            float a0 = As[ty * 4 + 0][k];
            float a1 = As[ty * 4 + 1][k];
            float a2 = As[ty * 4 + 2][k];
            float a3 = As[ty * 4 + 3][k];
#pragma unroll
            for (int c4 = 0; c4 < 5; c4++) {
                float4 b = *(const float4*)&Bs[k][jb + 4 * c4];
                acc[0][c4*4+0] = fmaf(a0, b.x, acc[0][c4*4+0]);
                acc[0][c4*4+1] = fmaf(a0, b.y, acc[0][c4*4+1]);
                acc[0][c4*4+2] = fmaf(a0, b.z, acc[0][c4*4+2]);
                acc[0][c4*4+3] = fmaf(a0, b.w, acc[0][c4*4+3]);
                acc[1][c4*4+0] = fmaf(a1, b.x, acc[1][c4*4+0]);
                acc[1][c4*4+1] = fmaf(a1, b.y, acc[1][c4*4+1]);
                acc[1][c4*4+2] = fmaf(a1, b.z, acc[1][c4*4+2]);
                acc[1][c4*4+3] = fmaf(a1, b.w, acc[1][c4*4+3]);
                acc[2][c4*4+0] = fmaf(a2, b.x, acc[2][c4*4+0]);
                acc[2][c4*4+1] = fmaf(a2, b.y, acc[2][c4*4+1]);
                acc[2][c4*4+2] = fmaf(a2, b.z, acc[2][c4*4+2]);
                acc[2][c4*4+3] = fmaf(a2, b.w, acc[2][c4*4+3]);
                acc[3][c4*4+0] = fmaf(a3, b.x, acc[3][c4*4+0]);
                acc[3][c4*4+1] = fmaf(a3, b.y, acc[3][c4*4+1]);
                acc[3][c4*4+2] = fmaf(a3, b.z, acc[3][c4*4+2]);
                acc[3][c4*4+3] = fmaf(a3, b.w, acc[3][c4*4+3]);
            }
        }
        __syncthreads();
    }

    // ---- epilogue ----
    if (jb >= DD) return;   // tx==15 owns the pad columns only

    float4 bb[5];
#pragma unroll
    for (int c4 = 0; c4 < 5; c4++) bb[c4] = *(const float4*)&bias[jb + 4 * c4];

#pragma unroll
    for (int r = 0; r < 4; r++) {
        int mg = row0 + ty * 4 + r;
        if (mg >= M) continue;
        const float* er = nullptr;
        if (EPI == E_EMB) er = emb + (long long)__ldg(&zidx[mg]) * DD;
#pragma unroll
        for (int c4 = 0; c4 < 5; c4++) {
            float4 o;
            o.x = acc[r][c4*4+0] + bb[c4].x;
            o.y = acc[r][c4*4+1] + bb[c4].y;
            o.z = acc[r][c4*4+2] + bb[c4].z;
            o.w = acc[r][c4*4+3] + bb[c4].w;
            if (EPI == E_EMB) {
                float4 ev = *(const float4*)&er[jb + 4 * c4];
                o.x += ev.x; o.y += ev.y; o.z += ev.z; o.w += ev.w;
            }
            if (EPI == E_RELU) {
                o.x = fmaxf(o.x, 0.f); o.y = fmaxf(o.y, 0.f);
                o.z = fmaxf(o.z, 0.f); o.w = fmaxf(o.w, 0.f);
            }
            *(float4*)&Out[(long long)mg * DD + jb + 4 * c4] = o;
        }
    }
}

// ---------------- h := x  (accumulator seed: folds "+ x" of GINE) ----------
__global__ void copy_x_to_h()
{
    int idx = blockIdx.x * 256 + threadIdx.x;
    if (idx < NN * F4C)
        ((float4*)g_h)[idx] = ((const float4*)g_x)[idx];
}

// ---------------- message pass: h[dst] += relu(x[src] + e) -----------------
__global__ void msg_kernel(const int* __restrict__ ei)
{
    long long idx = (long long)blockIdx.x * 256 + threadIdx.x;
    if (idx >= (long long)NE * F4C) return;
    int e  = (int)(idx / F4C);
    int c  = (int)(idx - (long long)e * F4C);
    int src = __ldg(ei + e);
    int dst = __ldg(ei + NE + e);
    float4 ev = __ldcs(((const float4*)g_e) + (long long)e * F4C + c); // stream, evict-first
    float4 xv = __ldg (((const float4*)g_x) + (long long)src * F4C + c); // keep x in L2
    float4 m;
    m.x = fmaxf(ev.x + xv.x, 0.f);
    m.y = fmaxf(ev.y + xv.y, 0.f);
    m.z = fmaxf(ev.z + xv.z, 0.f);
    m.w = fmaxf(ev.w + xv.w, 0.f);
    float* hp = g_h + (long long)dst * DD + c * 4;
    atomicAdd(hp + 0, m.x);
    atomicAdd(hp + 1, m.y);
    atomicAdd(hp + 2, m.z);
    atomicAdd(hp + 3, m.w);
}

// ---------------- x := LN(x + relu(h2)) ------------------------------------
__global__ void ln_kernel(const float* __restrict__ g, const float* __restrict__ b)
{
    int warp = threadIdx.x >> 5;
    int lane = threadIdx.x & 31;
    int row  = blockIdx.x * 8 + warp;
    if (row >= NN) return;
    const float* xr = g_x + (long long)row * DD;
    const float* hr = g_h + (long long)row * DD;

    float v[10];
    float s = 0.f;
#pragma unroll
    for (int i = 0; i < 10; i++) {
        int j = lane + 32 * i;
        if (j < DD) { v[i] = xr[j] + fmaxf(hr[j], 0.f); s += v[i]; }
        else          v[i] = 0.f;
    }
#pragma unroll
    for (int o = 16; o; o >>= 1) s += __shfl_xor_sync(0xffffffffu, s, o);
    float mu = s * (1.f / DD);

    float vs = 0.f;
#pragma unroll
    for (int i = 0; i < 10; i++) {
        int j = lane + 32 * i;
        if (j < DD) { float d = v[i] - mu; vs += d * d; }
    }
#pragma unroll
    for (int o = 16; o; o >>= 1) vs += __shfl_xor_sync(0xffffffffu, vs, o);
    float rstd = rsqrtf(vs * (1.f / DD) + 1e-5f);

    float* xw = g_x + (long long)row * DD;
#pragma unroll
    for (int i = 0; i < 10; i++) {
        int j = lane + 32 * i;
        if (j < DD) xw[j] = (v[i] - mu) * rstd * g[j] + b[j];
    }
}

// ---------------- pooling ---------------------------------------------------
__global__ void zero_pool()
{
    int idx = blockIdx.x * 256 + threadIdx.x;
    if (idx < NG * DD) g_pool[idx] = 0.f;
    if (idx < NG)      g_cnt[idx]  = 0.f;
}

__global__ void pool_accum(const int* __restrict__ batch)
{
    int idx = blockIdx.x * 256 + threadIdx.x;
    if (idx >= NN * F4C) return;
    int n = idx / F4C;
    int c = idx - n * F4C;
    int bg = __ldg(batch + n);
    float4 xv = ((const float4*)g_x)[idx];
    float* p = g_pool + bg * DD + c * 4;
    atomicAdd(p + 0, xv.x);
    atomicAdd(p + 1, xv.y);
    atomicAdd(p + 2, xv.z);
    atomicAdd(p + 3, xv.w);
    if (c == 0) atomicAdd(&g_cnt[bg], 1.f);
}

__global__ void pool_div()
{
    int idx = blockIdx.x * 256 + threadIdx.x;
    if (idx < NG * DD) g_pool[idx] /= fmaxf(g_cnt[idx / DD], 1.f);
}

// small dense GEMM for [256,K] @ [K,Nout] + b
__global__ void small_gemm(const float* __restrict__ A, const float* __restrict__ W,
                           const float* __restrict__ bias, float* __restrict__ O,
                           int K, int Nout)
{
    int j = blockIdx.x * blockDim.x + threadIdx.x;
    int g = blockIdx.y;
    if (j >= Nout) return;
    float s = bias[j];
    const float* ar = A + g * K;
    for (int k = 0; k < K; k++)
        s = fmaf(__ldg(ar + k), __ldg(&W[k * Nout + j]), s);
    O[g * Nout + j] = s;
}

// ============================================================
extern "C" void kernel_launch(void* const* d_in, const int* in_sizes, int n_in,
                              void* d_out, int out_size)
{
    const int*   z       = (const int*)  d_in[0];
    const float* chir    = (const float*)d_in[1];
    const float* fc      = (const float*)d_in[2];
    const int*   ei      = (const int*)  d_in[3];
    const float* ea      = (const float*)d_in[4];
    const int*   batch   = (const int*)  d_in[5];
    const float* atom_emb= (const float*)d_in[6];
    const float* nap_W1  = (const float*)d_in[7];
    const float* nap_b1  = (const float*)d_in[8];
    const float* nap_W2  = (const float*)d_in[9];
    const float* nap_b2  = (const float*)d_in[10];
    const float* ee_W1   = (const float*)d_in[11];
    const float* ee_b1   = (const float*)d_in[12];
    const float* ee_W2   = (const float*)d_in[13];
    const float* ee_b2   = (const float*)d_in[14];
    const float* gine_W1 = (const float*)d_in[15];
    const float* gine_b1 = (const float*)d_in[16];
    const float* gine_W2 = (const float*)d_in[17];
    const float* gine_b2 = (const float*)d_in[18];
    const float* ln_g    = (const float*)d_in[19];
    const float* ln_b    = (const float*)d_in[20];
    const float* pool_W  = (const float*)d_in[21];
    const float* pool_b  = (const float*)d_in[22];
    const float* proj_W  = (const float*)d_in[23];
    const float* proj_b  = (const float*)d_in[24];

    float *px, *ph, *phid, *pe, *ppool, *ppool2;
    cudaGetSymbolAddress((void**)&px,    g_x);
    cudaGetSymbolAddress((void**)&ph,    g_h);
    cudaGetSymbolAddress((void**)&phid,  g_hid);
    cudaGetSymbolAddress((void**)&pe,    g_e);
    cudaGetSymbolAddress((void**)&ppool, g_pool);
    cudaGetSymbolAddress((void**)&ppool2,g_pool2);

    const int gNode = (NN + BM - 1) / BM;     // 782
    const int gEdge = (NE + BM - 1) / BM;     // 12500
    const int gCopy = (NN * F4C + 255) / 256; // 14649
    const int gMsg  = (int)(((long long)NE * F4C + 255) / 256); // 234375
    const int gLN   = (NN + 7) / 8;           // 6250
    const int gPool = (NG * DD + 255) / 256;  // 300

    // 1. node init: x = relu(attr@W1+b1)@W2 + b2 + atom_emb[z]
    gemm300<A_NODE2, E_EMB><<<gNode, 256>>>(
        nullptr, chir, fc, nap_W1, nap_b1,
        nap_W2, nap_b2, atom_emb, z, px, NN);

    // 2. edge emb: e = relu(ea@W1+b1)@W2 + b2  (hidden fused, never stored)
    gemm300<A_EDGE3, E_BIAS><<<gEdge, 256>>>(
        nullptr, ea, nullptr, ee_W1, ee_b1,
        ee_W2, ee_b2, nullptr, nullptr, pe, NE);

    // 3. GINE layers
    for (int i = 0; i < NL; i++) {
        copy_x_to_h<<<gCopy, 256>>>();                 // h = x  (seed for "+x")
        msg_kernel<<<gMsg, 256>>>(ei);                 // h += scatter relu(x[src]+e)
        gemm300<A_GMEM, E_RELU><<<gNode, 256>>>(       // hid = relu(h@W1+b1)
            ph, nullptr, nullptr, nullptr, nullptr,
            gine_W1 + (long long)i * DD * DD, gine_b1 + i * DD,
            nullptr, nullptr, phid, NN);
        gemm300<A_GMEM, E_BIAS><<<gNode, 256>>>(       // h = hid@W2 + b2
            phid, nullptr, nullptr, nullptr, nullptr,
            gine_W2 + (long long)i * DD * DD, gine_b2 + i * DD,
            nullptr, nullptr, ph, NN);
        ln_kernel<<<gLN, 256>>>(ln_g + i * DD, ln_b + i * DD); // x = LN(x+relu(h))
    }

    // 4. pooling + projections
    zero_pool<<<gPool, 256>>>();
    pool_accum<<<gCopy, 256>>>(batch);
    pool_div<<<gPool, 256>>>();
    small_gemm<<<dim3(2, NG), 256>>>(ppool,  pool_W, pool_b, ppool2, DD, DD);
    small_gemm<<<dim3(3, NG), 256>>>(ppool2, proj_W, proj_b, (float*)d_out, DD, 600);
}

// round 6
// speedup vs baseline: 1.3811x; 1.3811x over previous
#include <cuda_runtime.h>
#include <cstdint>

// ---------------- problem constants ----------------
#define NN 50000
#define NE 800000
#define DD 300
#define NG 256
#define NL 5
#define F4C 75            // DD/4
#define KPAD 320          // weight k padding
#define NPAD 304          // weight n padding

// ---------------- GEMM tiling ----------------
#define BKT 16
#define NTIL 19           // 19*16 = 304 >= 300
#define AP 2560           // A plane floats: 128*20
#define BP 6080           // B plane floats: 304*20
#define BUFF 17280        // 2*AP + 2*BP
#define SMEM_BYTES (2*BUFF*4)   // 138240

// ---------------- scratch (static device arrays: allowed) ----------------
__device__ float g_x   [NN * DD];
__device__ float g_h   [NN * DD];
__device__ float g_hid [NN * DD];
__device__ float g_e   [(long long)NE * DD];   // 960 MB
__device__ float g_wth [11 * NPAD * KPAD];     // tf32 hi, [n][k]
__device__ float g_wtl [11 * NPAD * KPAD];     // tf32 lo, [n][k]
__device__ float g_pool [NG * DD];
__device__ float g_pool2[NG * DD];
__device__ float g_cnt  [NG];

enum { A_GMEM = 0, A_NODE2 = 1, A_EDGE3 = 2 };
enum { E_BIAS = 0, E_RELU = 1, E_EMB = 2 };

// ---------------- helpers ----------------
__device__ __forceinline__ uint32_t smem_u32(const void* p) {
    uint32_t a;
    asm("{ .reg .u64 t; cvta.to.shared.u64 t, %1; cvt.u32.u64 %0, t; }" : "=r"(a) : "l"(p));
    return a;
}
__device__ __forceinline__ float tf32h(float f) {
    uint32_t r; asm("cvt.rna.tf32.f32 %0, %1;" : "=r"(r) : "f"(f));
    return __uint_as_float(r);
}
#define CP_ASYNC16(dst, src) \
    asm volatile("cp.async.ca.shared.global [%0], [%1], 16;" :: "r"(dst), "l"(src) : "memory")
#define CP_COMMIT()  asm volatile("cp.async.commit_group;" ::: "memory")
#define CP_WAIT0()   asm volatile("cp.async.wait_group 0;" ::: "memory")

__device__ __forceinline__ void mma8(float* c, uint32_t a0, uint32_t a1, uint32_t a2,
                                     uint32_t a3, uint32_t b0, uint32_t b1) {
    asm volatile(
        "mma.sync.aligned.m16n8k8.row.col.f32.tf32.tf32.f32 "
        "{%0,%1,%2,%3}, {%4,%5,%6,%7}, {%8,%9}, {%0,%1,%2,%3};"
        : "+f"(c[0]), "+f"(c[1]), "+f"(c[2]), "+f"(c[3])
        : "r"(a0), "r"(a1), "r"(a2), "r"(a3), "r"(b0), "r"(b1));
}

// ---------------- weight prep: g_wth/g_wtl[mat] = split(W^T) ---------------
__global__ void prep_w(const float* __restrict__ W, int mat)
{
    int idx = blockIdx.x * 256 + threadIdx.x;
    if (idx >= NPAD * KPAD) return;
    int n = idx / KPAD, k = idx % KPAD;
    float v = (n < DD && k < DD) ? W[k * DD + n] : 0.f;
    float h = tf32h(v);
    g_wth[(long long)mat * NPAD * KPAD + idx] = h;
    g_wtl[(long long)mat * NPAD * KPAD + idx] = tf32h(v - h);
}

// ---------------- A tile generation (one float4 pair per thread) -----------
template<int ASRC>
__device__ __forceinline__ void gen_a(float4& vh, float4& vl, int row0, int k0, int M,
    const float* __restrict__ A, const float* __restrict__ s0,
    const float* __restrict__ s1, const float* __restrict__ aW1,
    const float* __restrict__ ab1, int tid)
{
    int row = tid >> 2, c4 = tid & 3;
    int mg = row0 + row, kg = k0 + c4 * 4;
    float4 f = make_float4(0.f, 0.f, 0.f, 0.f);
    if (mg < M && kg < DD) {
        if (ASRC == A_GMEM) {
            f = *(const float4*)&A[(long long)mg * DD + kg];
        } else if (ASRC == A_NODE2) {
            float a0 = __ldg(&s0[mg]), a1 = __ldg(&s1[mg]);
            float4 w0 = *(const float4*)&aW1[kg];
            float4 w1 = *(const float4*)&aW1[DD + kg];
            float4 bb = *(const float4*)&ab1[kg];
            f.x = fmaxf(a0*w0.x + a1*w1.x + bb.x, 0.f);
            f.y = fmaxf(a0*w0.y + a1*w1.y + bb.y, 0.f);
            f.z = fmaxf(a0*w0.z + a1*w1.z + bb.z, 0.f);
            f.w = fmaxf(a0*w0.w + a1*w1.w + bb.w, 0.f);
        } else {
            float e0 = __ldg(&s0[mg*3+0]), e1 = __ldg(&s0[mg*3+1]), e2 = __ldg(&s0[mg*3+2]);
            float4 w0 = *(const float4*)&aW1[kg];
            float4 w1 = *(const float4*)&aW1[DD + kg];
            float4 w2 = *(const float4*)&aW1[2*DD + kg];
            float4 bb = *(const float4*)&ab1[kg];
            f.x = fmaxf(e0*w0.x + e1*w1.x + e2*w2.x + bb.x, 0.f);
            f.y = fmaxf(e0*w0.y + e1*w1.y + e2*w2.y + bb.y, 0.f);
            f.z = fmaxf(e0*w0.z + e1*w1.z + e2*w2.z + bb.z, 0.f);
            f.w = fmaxf(e0*w0.w + e1*w1.w + e2*w2.w + bb.w, 0.f);
        }
    }
    vh.x = tf32h(f.x); vl.x = tf32h(f.x - vh.x);
    vh.y = tf32h(f.y); vl.y = tf32h(f.y - vh.y);
    vh.z = tf32h(f.z); vl.z = tf32h(f.z - vh.z);
    vh.w = tf32h(f.w); vl.w = tf32h(f.w - vh.w);
}

__device__ __forceinline__ void sts_a(float* buf, const float4& vh, const float4& vl, int tid)
{
    int row = tid >> 2, c4 = tid & 3;
    *(float4*)(buf + row * 20 + c4 * 4)      = vh;   // hi plane
    *(float4*)(buf + AP + row * 20 + c4 * 4) = vl;   // lo plane
}

__device__ __forceinline__ void issue_b(float* buf, const float* __restrict__ Bth,
                                        const float* __restrict__ Btl, int k0, int tid)
{
    float* bh = buf + 2 * AP;
    float* bl = bh + BP;
    // 2432 float4 total (hi 1216 + lo 1216); 512 threads -> 5 rounds (last partial)
#pragma unroll
    for (int i = 0; i < 5; i++) {
        int idx = tid + i * 512;
        if (idx >= 2432) break;
        int pl = (idx >= 1216);
        int j  = idx - pl * 1216;
        int n  = j >> 2, c4 = j & 3;
        const float* src = (pl ? Btl : Bth) + (long long)n * KPAD + k0 + c4 * 4;
        float* dstp = (pl ? bl : bh) + n * 20 + c4 * 4;
        CP_ASYNC16(smem_u32(dstp), src);
    }
}

// ============================================================
// tf32x3 mma.sync GEMM: Out[M,300] = Astage(M,300) @ W^T (+bias)(+emb)(relu?)
// CTA 128x304, 512 threads, 16 warps (8m x 2n), BK=16, double-buffered.
// ============================================================
template<int ASRC, int EPI>
__global__ __launch_bounds__(512, 1)
void mma_gemm(const float* __restrict__ A,
              const float* __restrict__ s0, const float* __restrict__ s1,
              const float* __restrict__ aW1, const float* __restrict__ ab1,
              const float* __restrict__ Bth, const float* __restrict__ Btl,
              const float* __restrict__ bias,
              const float* __restrict__ emb, const int* __restrict__ zidx,
              float* __restrict__ Out, int M)
{
    extern __shared__ float smem[];
    const int tid  = threadIdx.x;
    const int lane = tid & 31;
    const int wid  = tid >> 5;
    const int g    = lane >> 2;      // 0..7
    const int tg   = lane & 3;       // 0..3
    const int wm   = wid >> 1;       // 0..7
    const int wn   = wid & 1;        // 0..1
    const int row0 = blockIdx.x * 128;

    float acc[NTIL][4];
#pragma unroll
    for (int nt = 0; nt < NTIL; nt++)
#pragma unroll
        for (int i = 0; i < 4; i++) acc[nt][i] = 0.f;

    // prologue: tile 0
    {
        float4 vh, vl;
        gen_a<ASRC>(vh, vl, row0, 0, M, A, s0, s1, aW1, ab1, tid);
        sts_a(smem, vh, vl, tid);
        issue_b(smem, Bth, Btl, 0, tid);
        CP_COMMIT();
        CP_WAIT0();
    }
    __syncthreads();

    for (int t = 0; t < NTIL; t++) {
        const int cur = t & 1;
        const bool more = (t + 1 < NTIL);
        float* curb = smem + cur * BUFF;
        float* nxtb = smem + (cur ^ 1) * BUFF;

        float4 vh, vl;
        if (more) {
            issue_b(nxtb, Bth, Btl, (t + 1) * BKT, tid);
            CP_COMMIT();
            gen_a<ASRC>(vh, vl, row0, (t + 1) * BKT, M, A, s0, s1, aW1, ab1, tid);
        }

        // ---- compute on curb ----
        const float* Ah = curb;
        const float* Al = curb + AP;
        const float* Bh = curb + 2 * AP;
        const float* Bl = curb + 2 * AP + BP;
        const int abase = (wm * 16 + g) * 20 + tg;
        const int bbase = (wn * 152 + g) * 20 + tg;
#pragma unroll
        for (int ks = 0; ks < 2; ks++) {
            const int kk = ks * 8;
            uint32_t ah0 = __float_as_uint(Ah[abase + kk]);
            uint32_t ah1 = __float_as_uint(Ah[abase + kk + 160]);
            uint32_t ah2 = __float_as_uint(Ah[abase + kk + 4]);
            uint32_t ah3 = __float_as_uint(Ah[abase + kk + 164]);
            uint32_t al0 = __float_as_uint(Al[abase + kk]);
            uint32_t al1 = __float_as_uint(Al[abase + kk + 160]);
            uint32_t al2 = __float_as_uint(Al[abase + kk + 4]);
            uint32_t al3 = __float_as_uint(Al[abase + kk + 164]);
#pragma unroll
            for (int nt = 0; nt < NTIL; nt++) {
                const int bo = bbase + nt * 160 + kk;
                uint32_t b0h = __float_as_uint(Bh[bo]);
                uint32_t b1h = __float_as_uint(Bh[bo + 4]);
                uint32_t b0l = __float_as_uint(Bl[bo]);
                uint32_t b1l = __float_as_uint(Bl[bo + 4]);
                mma8(acc[nt], ah0, ah1, ah2, ah3, b0h, b1h);  // hi*hi
                mma8(acc[nt], al0, al1, al2, al3, b0h, b1h);  // lo*hi
                mma8(acc[nt], ah0, ah1, ah2, ah3, b0l, b1l);  // hi*lo
            }
        }

        if (more) {
            sts_a(nxtb, vh, vl, tid);
            CP_WAIT0();
        }
        __syncthreads();
    }

    // ---- epilogue ----
    const int r0 = row0 + wm * 16 + g;
    const int r1 = r0 + 8;
    const float* er0 = nullptr;
    const float* er1 = nullptr;
    if (EPI == E_EMB) {
        if (r0 < M) er0 = emb + (long long)__ldg(&zidx[r0]) * DD;
        if (r1 < M) er1 = emb + (long long)__ldg(&zidx[r1]) * DD;
    }
#pragma unroll
    for (int nt = 0; nt < NTIL; nt++) {
        const int col = wn * 152 + nt * 8 + tg * 2;
        if (col + 1 >= DD) continue;
        float2 bb = *(const float2*)&bias[col];
        if (r0 < M) {
            float2 o = make_float2(acc[nt][0] + bb.x, acc[nt][1] + bb.y);
            if (EPI == E_EMB) { float2 e = *(const float2*)&er0[col]; o.x += e.x; o.y += e.y; }
            if (EPI == E_RELU) { o.x = fmaxf(o.x, 0.f); o.y = fmaxf(o.y, 0.f); }
            *(float2*)&Out[(long long)r0 * DD + col] = o;
        }
        if (r1 < M) {
            float2 o = make_float2(acc[nt][2] + bb.x, acc[nt][3] + bb.y);
            if (EPI == E_EMB) { float2 e = *(const float2*)&er1[col]; o.x += e.x; o.y += e.y; }
            if (EPI == E_RELU) { o.x = fmaxf(o.x, 0.f); o.y = fmaxf(o.y, 0.f); }
            *(float2*)&Out[(long long)r1 * DD + col] = o;
        }
    }
}

// ---------------- h := x  (accumulator seed: folds "+ x" of GINE) ----------
__global__ void copy_x_to_h()
{
    int idx = blockIdx.x * 256 + threadIdx.x;
    if (idx < NN * F4C)
        ((float4*)g_h)[idx] = ((const float4*)g_x)[idx];
}

// ---------------- message pass: h[dst] += relu(x[src] + e) -----------------
__global__ void msg_kernel(const int* __restrict__ ei)
{
    long long idx = (long long)blockIdx.x * 256 + threadIdx.x;
    if (idx >= (long long)NE * F4C) return;
    int e  = (int)(idx / F4C);
    int c  = (int)(idx - (long long)e * F4C);
    int src = __ldg(ei + e);
    int dst = __ldg(ei + NE + e);
    float4 ev = __ldcs(((const float4*)g_e) + (long long)e * F4C + c);
    float4 xv = __ldg (((const float4*)g_x) + (long long)src * F4C + c);
    float4 m;
    m.x = fmaxf(ev.x + xv.x, 0.f);
    m.y = fmaxf(ev.y + xv.y, 0.f);
    m.z = fmaxf(ev.z + xv.z, 0.f);
    m.w = fmaxf(ev.w + xv.w, 0.f);
    float* hp = g_h + (long long)dst * DD + c * 4;
    atomicAdd(hp + 0, m.x);
    atomicAdd(hp + 1, m.y);
    atomicAdd(hp + 2, m.z);
    atomicAdd(hp + 3, m.w);
}

// ---------------- x := LN(x + relu(h2)) ------------------------------------
__global__ void ln_kernel(const float* __restrict__ g, const float* __restrict__ b)
{
    int warp = threadIdx.x >> 5;
    int lane = threadIdx.x & 31;
    int row  = blockIdx.x * 8 + warp;
    if (row >= NN) return;
    const float* xr = g_x + (long long)row * DD;
    const float* hr = g_h + (long long)row * DD;

    float v[10];
    float s = 0.f;
#pragma unroll
    for (int i = 0; i < 10; i++) {
        int j = lane + 32 * i;
        if (j < DD) { v[i] = xr[j] + fmaxf(hr[j], 0.f); s += v[i]; }
        else          v[i] = 0.f;
    }
#pragma unroll
    for (int o = 16; o; o >>= 1) s += __shfl_xor_sync(0xffffffffu, s, o);
    float mu = s * (1.f / DD);

    float vs = 0.f;
#pragma unroll
    for (int i = 0; i < 10; i++) {
        int j = lane + 32 * i;
        if (j < DD) { float d = v[i] - mu; vs += d * d; }
    }
#pragma unroll
    for (int o = 16; o; o >>= 1) vs += __shfl_xor_sync(0xffffffffu, vs, o);
    float rstd = rsqrtf(vs * (1.f / DD) + 1e-5f);

    float* xw = g_x + (long long)row * DD;
#pragma unroll
    for (int i = 0; i < 10; i++) {
        int j = lane + 32 * i;
        if (j < DD) xw[j] = (v[i] - mu) * rstd * g[j] + b[j];
    }
}

// ---------------- pooling ---------------------------------------------------
__global__ void zero_pool()
{
    int idx = blockIdx.x * 256 + threadIdx.x;
    if (idx < NG * DD) g_pool[idx] = 0.f;
    if (idx < NG)      g_cnt[idx]  = 0.f;
}

__global__ void pool_accum(const int* __restrict__ batch)
{
    int idx = blockIdx.x * 256 + threadIdx.x;
    if (idx >= NN * F4C) return;
    int n = idx / F4C;
    int c = idx - n * F4C;
    int bg = __ldg(batch + n);
    float4 xv = ((const float4*)g_x)[idx];
    float* p = g_pool + bg * DD + c * 4;
    atomicAdd(p + 0, xv.x);
    atomicAdd(p + 1, xv.y);
    atomicAdd(p + 2, xv.z);
    atomicAdd(p + 3, xv.w);
    if (c == 0) atomicAdd(&g_cnt[bg], 1.f);
}

__global__ void pool_div()
{
    int idx = blockIdx.x * 256 + threadIdx.x;
    if (idx < NG * DD) g_pool[idx] /= fmaxf(g_cnt[idx / DD], 1.f);
}

__global__ void small_gemm(const float* __restrict__ A, const float* __restrict__ W,
                           const float* __restrict__ bias, float* __restrict__ O,
                           int K, int Nout)
{
    int j = blockIdx.x * blockDim.x + threadIdx.x;
    int g = blockIdx.y;
    if (j >= Nout) return;
    float s = bias[j];
    const float* ar = A + g * K;
    for (int k = 0; k < K; k++)
        s = fmaf(__ldg(ar + k), __ldg(&W[k * Nout + j]), s);
    O[g * Nout + j] = s;
}

// ============================================================
extern "C" void kernel_launch(void* const* d_in, const int* in_sizes, int n_in,
                              void* d_out, int out_size)
{
    const int*   z       = (const int*)  d_in[0];
    const float* chir    = (const float*)d_in[1];
    const float* fc      = (const float*)d_in[2];
    const int*   ei      = (const int*)  d_in[3];
    const float* ea      = (const float*)d_in[4];
    const int*   batch   = (const int*)  d_in[5];
    const float* atom_emb= (const float*)d_in[6];
    const float* nap_W1  = (const float*)d_in[7];
    const float* nap_b1  = (const float*)d_in[8];
    const float* nap_W2  = (const float*)d_in[9];
    const float* nap_b2  = (const float*)d_in[10];
    const float* ee_W1   = (const float*)d_in[11];
    const float* ee_b1   = (const float*)d_in[12];
    const float* ee_W2   = (const float*)d_in[13];
    const float* ee_b2   = (const float*)d_in[14];
    const float* gine_W1 = (const float*)d_in[15];
    const float* gine_b1 = (const float*)d_in[16];
    const float* gine_W2 = (const float*)d_in[17];
    const float* gine_b2 = (const float*)d_in[18];
    const float* ln_g    = (const float*)d_in[19];
    const float* ln_b    = (const float*)d_in[20];
    const float* pool_W  = (const float*)d_in[21];
    const float* pool_b  = (const float*)d_in[22];
    const float* proj_W  = (const float*)d_in[23];
    const float* proj_b  = (const float*)d_in[24];

    float *px, *ph, *phid, *pe, *pwh, *pwl, *ppool, *ppool2;
    cudaGetSymbolAddress((void**)&px,    g_x);
    cudaGetSymbolAddress((void**)&ph,    g_h);
    cudaGetSymbolAddress((void**)&phid,  g_hid);
    cudaGetSymbolAddress((void**)&pe,    g_e);
    cudaGetSymbolAddress((void**)&pwh,   g_wth);
    cudaGetSymbolAddress((void**)&pwl,   g_wtl);
    cudaGetSymbolAddress((void**)&ppool, g_pool);
    cudaGetSymbolAddress((void**)&ppool2,g_pool2);

    cudaFuncSetAttribute(mma_gemm<A_NODE2, E_EMB>,  cudaFuncAttributeMaxDynamicSharedMemorySize, SMEM_BYTES);
    cudaFuncSetAttribute(mma_gemm<A_EDGE3, E_BIAS>, cudaFuncAttributeMaxDynamicSharedMemorySize, SMEM_BYTES);
    cudaFuncSetAttribute(mma_gemm<A_GMEM,  E_RELU>, cudaFuncAttributeMaxDynamicSharedMemorySize, SMEM_BYTES);
    cudaFuncSetAttribute(mma_gemm<A_GMEM,  E_BIAS>, cudaFuncAttributeMaxDynamicSharedMemorySize, SMEM_BYTES);

    const int gNode = (NN + 127) / 128;       // 391
    const int gEdge = NE / 128;               // 6250
    const int gCopy = (NN * F4C + 255) / 256;
    const int gMsg  = (int)(((long long)NE * F4C + 255) / 256);
    const int gLN   = (NN + 7) / 8;
    const int gPool = (NG * DD + 255) / 256;
    const int gPrep = (NPAD * KPAD + 255) / 256;
    const long long WSZ = (long long)NPAD * KPAD;

    // 0. weight prep: 0=nap_W2, 1=ee_W2, 2+i=gine_W1[i], 7+i=gine_W2[i]
    prep_w<<<gPrep, 256>>>(nap_W2, 0);
    prep_w<<<gPrep, 256>>>(ee_W2, 1);
    for (int i = 0; i < NL; i++) {
        prep_w<<<gPrep, 256>>>(gine_W1 + (long long)i * DD * DD, 2 + i);
        prep_w<<<gPrep, 256>>>(gine_W2 + (long long)i * DD * DD, 7 + i);
    }

    // 1. node init: x = relu(attr@W1+b1)@W2 + b2 + atom_emb[z]
    mma_gemm<A_NODE2, E_EMB><<<gNode, 512, SMEM_BYTES>>>(
        nullptr, chir, fc, nap_W1, nap_b1,
        pwh + 0 * WSZ, pwl + 0 * WSZ, nap_b2, atom_emb, z, px, NN);

    // 2. edge emb: e = relu(ea@W1+b1)@W2 + b2
    mma_gemm<A_EDGE3, E_BIAS><<<gEdge, 512, SMEM_BYTES>>>(
        nullptr, ea, nullptr, ee_W1, ee_b1,
        pwh + 1 * WSZ, pwl + 1 * WSZ, ee_b2, nullptr, nullptr, pe, NE);

    // 3. GINE layers
    for (int i = 0; i < NL; i++) {
        copy_x_to_h<<<gCopy, 256>>>();
        msg_kernel<<<gMsg, 256>>>(ei);
        mma_gemm<A_GMEM, E_RELU><<<gNode, 512, SMEM_BYTES>>>(
            ph, nullptr, nullptr, nullptr, nullptr,
            pwh + (2 + i) * WSZ, pwl + (2 + i) * WSZ, gine_b1 + i * DD,
            nullptr, nullptr, phid, NN);
        mma_gemm<A_GMEM, E_BIAS><<<gNode, 512, SMEM_BYTES>>>(
            phid, nullptr, nullptr, nullptr, nullptr,
            pwh + (7 + i) * WSZ, pwl + (7 + i) * WSZ, gine_b2 + i * DD,
            nullptr, nullptr, ph, NN);
        ln_kernel<<<gLN, 256>>>(ln_g + i * DD, ln_b + i * DD);
    }

    // 4. pooling + projections
    zero_pool<<<gPool, 256>>>();
    pool_accum<<<gCopy, 256>>>(batch);
    pool_div<<<gPool, 256>>>();
    small_gemm<<<dim3(2, NG), 256>>>(ppool,  pool_W, pool_b, ppool2, DD, DD);
    small_gemm<<<dim3(3, NG), 256>>>(ppool2, proj_W, proj_b, (float*)d_out, DD, 600);
}

// round 7
// speedup vs baseline: 2.7109x; 1.9629x over previous
#include <cuda_runtime.h>
#include <cstdint>

// ---------------- problem constants ----------------
#define NN 50000
#define NE 800000
#define DD 300
#define NG 256
#define NL 5
#define F4C 75            // DD/4
#define KPAD 320          // k padded: 10 tiles * 32
#define NPADB 320         // n padded: 4 warps * 80

// ---------------- GEMM tiling ----------------
#define BKT 32            // k per tile
#define NKT 10            // KPAD/BKT
#define NT_W 10           // n-frags per warp (80/8)
#define MT_W 2            // m-frags per warp (32/16)
// smem (words): A hi [128][20], A lo [128][20], B 2560 uint4
#define W_AH 0
#define W_AL 2560
#define W_B  5120
#define W_STAGE 15360     // 5120 + 10240
#define SMEM_BYTES (2*W_STAGE*4)   // 122880

// ---------------- scratch (static device arrays: allowed) ----------------
__device__ float g_x   [NN * DD];
__device__ float g_h   [NN * DD];
__device__ float g_hid [NN * DD];
__device__ float g_e   [(long long)NE * DD];     // 960 MB (dst-sorted rows)
__device__ uint4 g_wb  [11 * NKT * NPADB * 8];   // bf16 frag-major weights
__device__ int   g_cnt_i [NN];
__device__ int   g_rowptr[NN + 1];
__device__ int   g_cursor[NN];
__device__ int   g_slot  [NE];                   // edge -> sorted slot
__device__ int   g_srcs  [NE];                   // slot -> src node
__device__ float g_pool [NG * DD];
__device__ float g_pool2[NG * DD];
__device__ float g_cnt  [NG];

enum { A_GMEM = 0, A_NODE2 = 1, A_EDGE3 = 2 };
enum { E_BIAS = 0, E_RELU = 1, E_EMB = 2 };

// ---------------- helpers ----------------
__device__ __forceinline__ uint32_t smem_u32(const void* p) {
    uint32_t a;
    asm("{ .reg .u64 t; cvta.to.shared.u64 t, %1; cvt.u32.u64 %0, t; }" : "=r"(a) : "l"(p));
    return a;
}
__device__ __forceinline__ uint16_t bf16r(float f) {
    uint16_t u; asm("cvt.rn.bf16.f32 %0, %1;" : "=h"(u) : "f"(f)); return u;
}
__device__ __forceinline__ float bf2f(uint16_t u) {
    return __uint_as_float(((uint32_t)u) << 16);
}
__device__ __forceinline__ uint32_t packbf(uint16_t lo, uint16_t hi) {
    return ((uint32_t)hi << 16) | lo;
}
#define CP_ASYNC16(dst, src) \
    asm volatile("cp.async.ca.shared.global [%0], [%1], 16;" :: "r"(dst), "l"(src) : "memory")
#define CP_COMMIT()  asm volatile("cp.async.commit_group;" ::: "memory")
#define CP_WAIT0()   asm volatile("cp.async.wait_group 0;" ::: "memory")

__device__ __forceinline__ void mma_bf16(float* c, uint32_t a0, uint32_t a1, uint32_t a2,
                                         uint32_t a3, uint32_t b0, uint32_t b1) {
    asm volatile(
        "mma.sync.aligned.m16n8k16.row.col.f32.bf16.bf16.f32 "
        "{%0,%1,%2,%3}, {%4,%5,%6,%7}, {%8,%9}, {%0,%1,%2,%3};"
        : "+f"(c[0]), "+f"(c[1]), "+f"(c[2]), "+f"(c[3])
        : "r"(a0), "r"(a1), "r"(a2), "r"(a3), "r"(b0), "r"(b1));
}

// ---------------- weight prep: frag-major bf16 hi/lo chunks ----------------
// chunk (kt, n, slot): slot = (ks*4+tg) ^ ((n&1)*4); 16B = {b0h,b1h,b0l,b1l}
// b0 = W^T[n][k0..k0+1], b1 = W^T[n][k0+8..k0+9], k0 = kt*32 + ks*16 + 2*tg
__global__ void prep_w(const float* __restrict__ W, int mat)
{
    int idx = blockIdx.x * 256 + threadIdx.x;
    if (idx >= NKT * NPADB * 8) return;
    int kt = idx / (NPADB * 8);
    int r  = idx - kt * NPADB * 8;
    int n  = r >> 3;
    int slot = r & 7;
    int ks = ((slot ^ ((n & 1) * 4)) >> 2) & 1;
    int tg = slot & 3;
    int k0 = kt * 32 + ks * 16 + 2 * tg;

    float v[4];
#pragma unroll
    for (int j = 0; j < 4; j++) {
        int k = k0 + (j >> 1) * 8 + (j & 1);
        v[j] = (n < DD && k < DD) ? W[k * DD + n] : 0.f;
    }
    uint16_t h[4], l[4];
#pragma unroll
    for (int j = 0; j < 4; j++) {
        h[j] = bf16r(v[j]);
        l[j] = bf16r(v[j] - bf2f(h[j]));
    }
    uint4 out;
    out.x = packbf(h[0], h[1]);   // b0h
    out.y = packbf(h[2], h[3]);   // b1h
    out.z = packbf(l[0], l[1]);   // b0l
    out.w = packbf(l[2], l[3]);   // b1l
    g_wb[(long long)mat * NKT * NPADB * 8 + idx] = out;
}

// ---------------- A tile generation: 8 k-values per thread -----------------
template<int ASRC>
__device__ __forceinline__ void gen_a(uint4& oh, uint4& ol, int row0, int k0t, int M,
    const float* __restrict__ A, const float* __restrict__ s0,
    const float* __restrict__ s1, const float* __restrict__ aW1,
    const float* __restrict__ ab1, int tid)
{
    int row = tid >> 2, c4 = tid & 3;
    int mg = row0 + row;
    float f[8];
#pragma unroll
    for (int j = 0; j < 8; j++) f[j] = 0.f;
    if (mg < M) {
#pragma unroll
        for (int half = 0; half < 2; half++) {
            int kg = k0t + c4 * 8 + half * 4;
            if (kg < DD) {
                if (ASRC == A_GMEM) {
                    float4 v = *(const float4*)&A[(long long)mg * DD + kg];
                    f[half*4+0] = v.x; f[half*4+1] = v.y; f[half*4+2] = v.z; f[half*4+3] = v.w;
                } else if (ASRC == A_NODE2) {
                    float a0 = __ldg(&s0[mg]), a1 = __ldg(&s1[mg]);
                    float4 w0 = *(const float4*)&aW1[kg];
                    float4 w1 = *(const float4*)&aW1[DD + kg];
                    float4 bb = *(const float4*)&ab1[kg];
                    f[half*4+0] = fmaxf(a0*w0.x + a1*w1.x + bb.x, 0.f);
                    f[half*4+1] = fmaxf(a0*w0.y + a1*w1.y + bb.y, 0.f);
                    f[half*4+2] = fmaxf(a0*w0.z + a1*w1.z + bb.z, 0.f);
                    f[half*4+3] = fmaxf(a0*w0.w + a1*w1.w + bb.w, 0.f);
                } else {
                    float e0 = __ldg(&s0[mg*3+0]), e1 = __ldg(&s0[mg*3+1]), e2 = __ldg(&s0[mg*3+2]);
                    float4 w0 = *(const float4*)&aW1[kg];
                    float4 w1 = *(const float4*)&aW1[DD + kg];
                    float4 w2 = *(const float4*)&aW1[2*DD + kg];
                    float4 bb = *(const float4*)&ab1[kg];
                    f[half*4+0] = fmaxf(e0*w0.x + e1*w1.x + e2*w2.x + bb.x, 0.f);
                    f[half*4+1] = fmaxf(e0*w0.y + e1*w1.y + e2*w2.y + bb.y, 0.f);
                    f[half*4+2] = fmaxf(e0*w0.z + e1*w1.z + e2*w2.z + bb.z, 0.f);
                    f[half*4+3] = fmaxf(e0*w0.w + e1*w1.w + e2*w2.w + bb.w, 0.f);
                }
            }
        }
    }
    uint16_t h[8], l[8];
#pragma unroll
    for (int j = 0; j < 8; j++) {
        h[j] = bf16r(f[j]);
        l[j] = bf16r(f[j] - bf2f(h[j]));
    }
    oh = make_uint4(packbf(h[0],h[1]), packbf(h[2],h[3]), packbf(h[4],h[5]), packbf(h[6],h[7]));
    ol = make_uint4(packbf(l[0],l[1]), packbf(l[2],l[3]), packbf(l[4],l[5]), packbf(l[6],l[7]));
}

__device__ __forceinline__ void sts_a(uint32_t* sw, const uint4& oh, const uint4& ol, int tid)
{
    int row = tid >> 2, c4 = tid & 3;
    int w = row * 20 + c4 * 4;
    *(uint4*)(sw + W_AH + w) = oh;
    *(uint4*)(sw + W_AL + w) = ol;
}

__device__ __forceinline__ void issue_b(uint32_t* sw, const uint4* __restrict__ Bt,
                                        int kt, int tid)
{
    const uint4* src = Bt + (long long)kt * NPADB * 8;
    uint32_t dbase = smem_u32(sw + W_B);
#pragma unroll
    for (int i = 0; i < 5; i++) {
        int idx = tid + i * 512;
        CP_ASYNC16(dbase + idx * 16, src + idx);
    }
}

// ============================================================
// bf16x3 mma.sync GEMM: Out[M,300] = Astage(M,300) @ W^T (+bias)(+emb)(relu?)
// CTA 128x320, 512 threads, 16 warps (4m x 4n), BK=32, double-buffered.
// ============================================================
template<int ASRC, int EPI, bool PERM>
__global__ __launch_bounds__(512, 1)
void mma_gemm(const float* __restrict__ A,
              const float* __restrict__ s0, const float* __restrict__ s1,
              const float* __restrict__ aW1, const float* __restrict__ ab1,
              const uint4* __restrict__ Bt, const float* __restrict__ bias,
              const float* __restrict__ emb, const int* __restrict__ zidx,
              const int* __restrict__ perm,
              float* __restrict__ Out, int M)
{
    extern __shared__ uint32_t sw[];
    const int tid  = threadIdx.x;
    const int lane = tid & 31;
    const int wid  = tid >> 5;
    const int g    = lane >> 2;      // 0..7
    const int tg   = lane & 3;       // 0..3
    const int wm   = wid >> 2;       // 0..3  -> rows wm*32
    const int wn   = wid & 3;        // 0..3  -> cols wn*80
    const int row0 = blockIdx.x * 128;

    float acc[MT_W][NT_W][4];
#pragma unroll
    for (int mt = 0; mt < MT_W; mt++)
#pragma unroll
        for (int nt = 0; nt < NT_W; nt++)
#pragma unroll
            for (int i = 0; i < 4; i++) acc[mt][nt][i] = 0.f;

    // prologue
    {
        uint4 oh, ol;
        gen_a<ASRC>(oh, ol, row0, 0, M, A, s0, s1, aW1, ab1, tid);
        sts_a(sw, oh, ol, tid);
        issue_b(sw, Bt, 0, tid);
        CP_COMMIT();
        CP_WAIT0();
    }
    __syncthreads();

    for (int t = 0; t < NKT; t++) {
        uint32_t* cur = sw + (t & 1) * W_STAGE;
        uint32_t* nxt = sw + ((t & 1) ^ 1) * W_STAGE;
        const bool more = (t + 1 < NKT);

        uint4 oh, ol;
        if (more) {
            issue_b(nxt, Bt, t + 1, tid);
            CP_COMMIT();
            gen_a<ASRC>(oh, ol, row0, (t + 1) * BKT, M, A, s0, s1, aW1, ab1, tid);
        }

        // ---- compute ----
        const uint32_t* AH = cur + W_AH;
        const uint32_t* AL = cur + W_AL;
        const uint32_t* BB = cur + W_B;
#pragma unroll
        for (int ks = 0; ks < 2; ks++) {
            uint32_t aH[MT_W][4], aL[MT_W][4];
#pragma unroll
            for (int mt = 0; mt < MT_W; mt++) {
                int rbase = (wm * 32 + mt * 16 + g) * 20 + ks * 8 + tg;
                aH[mt][0] = AH[rbase];
                aH[mt][1] = AH[rbase + 160];
                aH[mt][2] = AH[rbase + 4];
                aH[mt][3] = AH[rbase + 164];
                aL[mt][0] = AL[rbase];
                aL[mt][1] = AL[rbase + 160];
                aL[mt][2] = AL[rbase + 4];
                aL[mt][3] = AL[rbase + 164];
            }
            const int slot = (ks * 4 + tg) ^ ((g & 1) * 4);
#pragma unroll
            for (int nt = 0; nt < NT_W; nt++) {
                int n = wn * 80 + nt * 8 + g;
                uint4 b = *(const uint4*)(BB + (n * 8 + slot) * 4);
#pragma unroll
                for (int mt = 0; mt < MT_W; mt++) {
                    mma_bf16(acc[mt][nt], aH[mt][0], aH[mt][1], aH[mt][2], aH[mt][3], b.x, b.y); // hi*hi
                    mma_bf16(acc[mt][nt], aL[mt][0], aL[mt][1], aL[mt][2], aL[mt][3], b.x, b.y); // lo*hi
                    mma_bf16(acc[mt][nt], aH[mt][0], aH[mt][1], aH[mt][2], aH[mt][3], b.z, b.w); // hi*lo
                }
            }
        }

        if (more) {
            sts_a(nxt, oh, ol, tid);
            CP_WAIT0();
        }
        __syncthreads();
    }

    // ---- epilogue ----
#pragma unroll
    for (int mt = 0; mt < MT_W; mt++) {
        int r0 = row0 + wm * 32 + mt * 16 + g;
        int r1 = r0 + 8;
        const float* er0 = nullptr;
        const float* er1 = nullptr;
        if (EPI == E_EMB) {
            if (r0 < M) er0 = emb + (long long)__ldg(&zidx[r0]) * DD;
            if (r1 < M) er1 = emb + (long long)__ldg(&zidx[r1]) * DD;
        }
        long long o0 = 0, o1 = 0;
        if (r0 < M) o0 = (long long)(PERM ? __ldg(&perm[r0]) : r0) * DD;
        if (r1 < M) o1 = (long long)(PERM ? __ldg(&perm[r1]) : r1) * DD;
#pragma unroll
        for (int nt = 0; nt < NT_W; nt++) {
            int col = wn * 80 + nt * 8 + tg * 2;
            if (col >= DD) continue;
            float2 bb = *(const float2*)&bias[col];
            if (r0 < M) {
                float2 o = make_float2(acc[mt][nt][0] + bb.x, acc[mt][nt][1] + bb.y);
                if (EPI == E_EMB) { float2 e = *(const float2*)&er0[col]; o.x += e.x; o.y += e.y; }
                if (EPI == E_RELU) { o.x = fmaxf(o.x, 0.f); o.y = fmaxf(o.y, 0.f); }
                *(float2*)&Out[o0 + col] = o;
            }
            if (r1 < M) {
                float2 o = make_float2(acc[mt][nt][2] + bb.x, acc[mt][nt][3] + bb.y);
                if (EPI == E_EMB) { float2 e = *(const float2*)&er1[col]; o.x += e.x; o.y += e.y; }
                if (EPI == E_RELU) { o.x = fmaxf(o.x, 0.f); o.y = fmaxf(o.y, 0.f); }
                *(float2*)&Out[o1 + col] = o;
            }
        }
    }
}

// ---------------- CSR build (per launch) -----------------------------------
__global__ void zero_cnt()
{
    int i = blockIdx.x * 256 + threadIdx.x;
    if (i < NN) g_cnt_i[i] = 0;
}
__global__ void count_k(const int* __restrict__ ei)
{
    int e = blockIdx.x * 256 + threadIdx.x;
    if (e < NE) atomicAdd(&g_cnt_i[__ldg(ei + NE + e)], 1);
}
__global__ void scan_k()
{
    __shared__ int sm[1024];
    __shared__ int carry;
    int t = threadIdx.x;
    if (t == 0) carry = 0;
    __syncthreads();
    for (int base = 0; base < NN; base += 1024) {
        int i = base + t;
        int v = (i < NN) ? g_cnt_i[i] : 0;
        sm[t] = v;
        __syncthreads();
        for (int off = 1; off < 1024; off <<= 1) {
            int u = (t >= off) ? sm[t - off] : 0;
            __syncthreads();
            sm[t] += u;
            __syncthreads();
        }
        int exc = sm[t] - v + carry;
        if (i < NN) { g_rowptr[i] = exc; g_cursor[i] = exc; }
        __syncthreads();
        if (t == 1023) carry += sm[1023];
        __syncthreads();
    }
    if (t == 0) g_rowptr[NN] = carry;
}
__global__ void scatter_k(const int* __restrict__ ei)
{
    int e = blockIdx.x * 256 + threadIdx.x;
    if (e >= NE) return;
    int d = __ldg(ei + NE + e);
    int pos = atomicAdd(&g_cursor[d], 1);
    g_slot[e] = pos;
    g_srcs[pos] = __ldg(ei + e);
}

// ---------------- message pass: h[d] = x[d] + sum relu(x[src]+e) -----------
__global__ __launch_bounds__(96)
void msg_csr()
{
    int d = blockIdx.x;
    int t = threadIdx.x;
    if (t >= F4C) return;
    int beg = g_rowptr[d];
    int end = g_rowptr[d + 1];
    float4 acc = ((const float4*)g_x)[(long long)d * F4C + t];
    for (int j = beg; j < end; j++) {
        int s = __ldg(&g_srcs[j]);
        float4 ev = __ldcs(((const float4*)g_e) + (long long)j * F4C + t);
        float4 xv = __ldg (((const float4*)g_x) + (long long)s * F4C + t);
        acc.x += fmaxf(ev.x + xv.x, 0.f);
        acc.y += fmaxf(ev.y + xv.y, 0.f);
        acc.z += fmaxf(ev.z + xv.z, 0.f);
        acc.w += fmaxf(ev.w + xv.w, 0.f);
    }
    ((float4*)g_h)[(long long)d * F4C + t] = acc;
}

// ---------------- x := LN(x + relu(h2)) ------------------------------------
__global__ void ln_kernel(const float* __restrict__ g, const float* __restrict__ b)
{
    int warp = threadIdx.x >> 5;
    int lane = threadIdx.x & 31;
    int row  = blockIdx.x * 8 + warp;
    if (row >= NN) return;
    const float* xr = g_x + (long long)row * DD;
    const float* hr = g_h + (long long)row * DD;

    float v[10];
    float s = 0.f;
#pragma unroll
    for (int i = 0; i < 10; i++) {
        int j = lane + 32 * i;
        if (j < DD) { v[i] = xr[j] + fmaxf(hr[j], 0.f); s += v[i]; }
        else          v[i] = 0.f;
    }
#pragma unroll
    for (int o = 16; o; o >>= 1) s += __shfl_xor_sync(0xffffffffu, s, o);
    float mu = s * (1.f / DD);

    float vs = 0.f;
#pragma unroll
    for (int i = 0; i < 10; i++) {
        int j = lane + 32 * i;
        if (j < DD) { float d = v[i] - mu; vs += d * d; }
    }
#pragma unroll
    for (int o = 16; o; o >>= 1) vs += __shfl_xor_sync(0xffffffffu, vs, o);
    float rstd = rsqrtf(vs * (1.f / DD) + 1e-5f);

    float* xw = g_x + (long long)row * DD;
#pragma unroll
    for (int i = 0; i < 10; i++) {
        int j = lane + 32 * i;
        if (j < DD) xw[j] = (v[i] - mu) * rstd * g[j] + b[j];
    }
}

// ---------------- pooling ---------------------------------------------------
__global__ void zero_pool()
{
    int idx = blockIdx.x * 256 + threadIdx.x;
    if (idx < NG * DD) g_pool[idx] = 0.f;
    if (idx < NG)      g_cnt[idx]  = 0.f;
}
__global__ void pool_accum(const int* __restrict__ batch)
{
    int idx = blockIdx.x * 256 + threadIdx.x;
    if (idx >= NN * F4C) return;
    int n = idx / F4C;
    int c = idx - n * F4C;
    int bg = __ldg(batch + n);
    float4 xv = ((const float4*)g_x)[idx];
    float* p = g_pool + bg * DD + c * 4;
    atomicAdd(p + 0, xv.x);
    atomicAdd(p + 1, xv.y);
    atomicAdd(p + 2, xv.z);
    atomicAdd(p + 3, xv.w);
    if (c == 0) atomicAdd(&g_cnt[bg], 1.f);
}
__global__ void pool_div()
{
    int idx = blockIdx.x * 256 + threadIdx.x;
    if (idx < NG * DD) g_pool[idx] /= fmaxf(g_cnt[idx / DD], 1.f);
}
__global__ void small_gemm(const float* __restrict__ A, const float* __restrict__ W,
                           const float* __restrict__ bias, float* __restrict__ O,
                           int K, int Nout)
{
    int j = blockIdx.x * blockDim.x + threadIdx.x;
    int g = blockIdx.y;
    if (j >= Nout) return;
    float s = bias[j];
    const float* ar = A + g * K;
    for (int k = 0; k < K; k++)
        s = fmaf(__ldg(ar + k), __ldg(&W[k * Nout + j]), s);
    O[g * Nout + j] = s;
}

// ============================================================
extern "C" void kernel_launch(void* const* d_in, const int* in_sizes, int n_in,
                              void* d_out, int out_size)
{
    const int*   z       = (const int*)  d_in[0];
    const float* chir    = (const float*)d_in[1];
    const float* fc      = (const float*)d_in[2];
    const int*   ei      = (const int*)  d_in[3];
    const float* ea      = (const float*)d_in[4];
    const int*   batch   = (const int*)  d_in[5];
    const float* atom_emb= (const float*)d_in[6];
    const float* nap_W1  = (const float*)d_in[7];
    const float* nap_b1  = (const float*)d_in[8];
    const float* nap_W2  = (const float*)d_in[9];
    const float* nap_b2  = (const float*)d_in[10];
    const float* ee_W1   = (const float*)d_in[11];
    const float* ee_b1   = (const float*)d_in[12];
    const float* ee_W2   = (const float*)d_in[13];
    const float* ee_b2   = (const float*)d_in[14];
    const float* gine_W1 = (const float*)d_in[15];
    const float* gine_b1 = (const float*)d_in[16];
    const float* gine_W2 = (const float*)d_in[17];
    const float* gine_b2 = (const float*)d_in[18];
    const float* ln_g    = (const float*)d_in[19];
    const float* ln_b    = (const float*)d_in[20];
    const float* pool_W  = (const float*)d_in[21];
    const float* pool_b  = (const float*)d_in[22];
    const float* proj_W  = (const float*)d_in[23];
    const float* proj_b  = (const float*)d_in[24];

    float *px, *ph, *phid, *pe, *ppool, *ppool2;
    uint4 *pwb;
    int   *pslot;
    cudaGetSymbolAddress((void**)&px,    g_x);
    cudaGetSymbolAddress((void**)&ph,    g_h);
    cudaGetSymbolAddress((void**)&phid,  g_hid);
    cudaGetSymbolAddress((void**)&pe,    g_e);
    cudaGetSymbolAddress((void**)&pwb,   g_wb);
    cudaGetSymbolAddress((void**)&pslot, g_slot);
    cudaGetSymbolAddress((void**)&ppool, g_pool);
    cudaGetSymbolAddress((void**)&ppool2,g_pool2);

    cudaFuncSetAttribute(mma_gemm<A_NODE2, E_EMB,  false>, cudaFuncAttributeMaxDynamicSharedMemorySize, SMEM_BYTES);
    cudaFuncSetAttribute(mma_gemm<A_EDGE3, E_BIAS, true >, cudaFuncAttributeMaxDynamicSharedMemorySize, SMEM_BYTES);
    cudaFuncSetAttribute(mma_gemm<A_GMEM,  E_RELU, false>, cudaFuncAttributeMaxDynamicSharedMemorySize, SMEM_BYTES);
    cudaFuncSetAttribute(mma_gemm<A_GMEM,  E_BIAS, false>, cudaFuncAttributeMaxDynamicSharedMemorySize, SMEM_BYTES);

    const int gNode = (NN + 127) / 128;       // 391
    const int gEdge = NE / 128;               // 6250
    const int gNNv  = (NN * F4C + 255) / 256;
    const int gLN   = (NN + 7) / 8;
    const int gPool = (NG * DD + 255) / 256;
    const int gPrep = (NKT * NPADB * 8 + 255) / 256;   // 100
    const int gNNi  = (NN + 255) / 256;
    const int gNEi  = (NE + 255) / 256;
    const long long WSZ = (long long)NKT * NPADB * 8;

    // 0a. CSR build (edge topology is launch-invariant data, rebuilt per call)
    zero_cnt<<<gNNi, 256>>>();
    count_k<<<gNEi, 256>>>(ei);
    scan_k<<<1, 1024>>>();
    scatter_k<<<gNEi, 256>>>(ei);

    // 0b. weight prep: 0=nap_W2, 1=ee_W2, 2+i=gine_W1[i], 7+i=gine_W2[i]
    prep_w<<<gPrep, 256>>>(nap_W2, 0);
    prep_w<<<gPrep, 256>>>(ee_W2, 1);
    for (int i = 0; i < NL; i++) {
        prep_w<<<gPrep, 256>>>(gine_W1 + (long long)i * DD * DD, 2 + i);
        prep_w<<<gPrep, 256>>>(gine_W2 + (long long)i * DD * DD, 7 + i);
    }

    // 1. node init: x = relu(attr@W1+b1)@W2 + b2 + atom_emb[z]
    mma_gemm<A_NODE2, E_EMB, false><<<gNode, 512, SMEM_BYTES>>>(
        nullptr, chir, fc, nap_W1, nap_b1,
        pwb + 0 * WSZ, nap_b2, atom_emb, z, nullptr, px, NN);

    // 2. edge emb (rows written at dst-sorted slots)
    mma_gemm<A_EDGE3, E_BIAS, true><<<gEdge, 512, SMEM_BYTES>>>(
        nullptr, ea, nullptr, ee_W1, ee_b1,
        pwb + 1 * WSZ, ee_b2, nullptr, nullptr, pslot, pe, NE);

    // 3. GINE layers
    for (int i = 0; i < NL; i++) {
        msg_csr<<<NN, 96>>>();                       // h = x + sum relu(x[src]+e)
        mma_gemm<A_GMEM, E_RELU, false><<<gNode, 512, SMEM_BYTES>>>(
            ph, nullptr, nullptr, nullptr, nullptr,
            pwb + (2 + i) * WSZ, gine_b1 + i * DD, nullptr, nullptr, nullptr, phid, NN);
        mma_gemm<A_GMEM, E_BIAS, false><<<gNode, 512, SMEM_BYTES>>>(
            phid, nullptr, nullptr, nullptr, nullptr,
            pwb + (7 + i) * WSZ, gine_b2 + i * DD, nullptr, nullptr, nullptr, ph, NN);
        ln_kernel<<<gLN, 256>>>(ln_g + i * DD, ln_b + i * DD);
    }

    // 4. pooling + projections
    zero_pool<<<gPool, 256>>>();
    pool_accum<<<gNNv, 256>>>(batch);
    pool_div<<<gPool, 256>>>();
    small_gemm<<<dim3(2, NG), 256>>>(ppool,  pool_W, pool_b, ppool2, DD, DD);
    small_gemm<<<dim3(3, NG), 256>>>(ppool2, proj_W, proj_b, (float*)d_out, DD, 600);
}